// round 15
// baseline (speedup 1.0000x reference)
#include <cuda_runtime.h>
#include <cuda_fp16.h>
#include <math.h>
#include <stdint.h>

#define Bb   256
#define Ss   32
#define VFd  512
#define IFd  256
#define Ff   768
#define Hh   1024
#define Ll   2
#define Kk   8
#define MB   (Ll*Bb)
#define G3F  (3*Ff)

#define BM 64
#define BN 64
#define BK 256
#define NTHR 512
#define ROWB   528
#define PLANE  (64*ROWB)       // 33792
#define STAGE_BYTES (2*PLANE)  // 67584
#define NSTAGE 3
#define RMW_OFF (NSTAGE*STAGE_BYTES)            // 202752
#define SMEM_TOTAL (NSTAGE*STAGE_BYTES + 16384) // 219136

__device__ __align__(16) float  g_dt  [Ss*Bb];
__device__ __align__(16) float  g_Y   [MB*Ff];
__device__ __align__(16) __half g_Yh  [MB*Ff];
__device__ __align__(16) __half g_xh  [Ss*Bb*Ff];
__device__ __align__(16) float  g_a1  [MB*Hh];
__device__ __align__(16) __half g_h1h [MB*Hh];
__device__ __align__(16) __half g_h2h [MB*Hh];
__device__ __align__(16) float  g_Sf  [MB*Hh];
__device__ __align__(16) __half g_Sh  [MB*Hh];
__device__ __align__(16) __half g_x1h [Bb*Ff];
__device__ __align__(16) __half g_outh[Ss*Bb*Ff];
__device__ __align__(16) float  g_gx0 [Ss*Bb*G3F];
__device__ __align__(16) float  g_gh  [2*Bb*G3F];
__device__ __align__(16) float  g_gx1 [Bb*G3F];
__device__ __align__(16) float  g_hid [Ss*Bb*128];
__device__ __align__(16) float  g_c0  [Hh];
__device__ __align__(16) __half g_W0h [Hh*Ff];
__device__ __align__(16) __half g_W1h [Hh*Hh];
__device__ __align__(16) __half g_W2h [Ff*Hh];
__device__ __align__(16) __half g_W2Th[Hh*Ff];
__device__ __align__(16) float  g_W20f[Hh*Hh];
__device__ __align__(16) __half g_W20h[Hh*Hh];
__device__ __align__(16) __half g_Wxh [Ll*G3F*Ff];
__device__ __align__(16) __half g_Whh [Ll*G3F*Ff];
__device__ __align__(16) __half g_rW1h[128*Ff];
__device__ unsigned g_rowcnt[8];

__device__ __forceinline__ uint32_t smem_u32(const void* p) {
    uint32_t a;
    asm("{ .reg .u64 t; cvta.to.shared.u64 t, %1; cvt.u32.u64 %0, t; }" : "=r"(a) : "l"(p));
    return a;
}
__device__ __forceinline__ void cp16(uint32_t dst, const void* src) {
    asm volatile("cp.async.cg.shared.global [%0], [%1], 16;" :: "r"(dst), "l"(src));
}
__device__ __forceinline__ void ldm_x4(uint32_t addr, uint32_t r[4]) {
    asm volatile("ldmatrix.sync.aligned.m8n8.x4.shared.b16 {%0,%1,%2,%3}, [%4];"
                 : "=r"(r[0]), "=r"(r[1]), "=r"(r[2]), "=r"(r[3]) : "r"(addr));
}
__device__ __forceinline__ void mma16816(float d[4], const uint32_t a[4],
                                         uint32_t b0, uint32_t b1) {
    asm volatile("mma.sync.aligned.m16n8k16.row.col.f32.f16.f16.f32 "
                 "{%0,%1,%2,%3}, {%4,%5,%6,%7}, {%8,%9}, {%0,%1,%2,%3};"
                 : "+f"(d[0]), "+f"(d[1]), "+f"(d[2]), "+f"(d[3])
                 : "r"(a[0]), "r"(a[1]), "r"(a[2]), "r"(a[3]), "r"(b0), "r"(b1));
}

enum { EPI_STORE = 0, EPI_LRELU, EPI_A1, EPI_H2, EPI_DA1, EPI_YUPD };

// ---------------- standalone 64x64 GEMM core (unchanged from R14) ----------------
template<int EPI, int KMODE>
__device__ __forceinline__ void gemm_core(
    const __half* __restrict__ A, int lda,
    const __half* __restrict__ Bm, int ldb,
    const float* __restrict__ bias,
    int m0, int n0, int Kd,
    float* __restrict__ Cf, int ldc,
    const float* __restrict__ dtv)
{
    extern __shared__ char smem[];
    __shared__ float sbias[BN];
    __shared__ float sdt[BM];
    const uint32_t smem_base = smem_u32(smem);
    const int tid = threadIdx.x;
    const int wid = tid >> 5, lane = tid & 31;
    const int warp_m = wid & 3;
    const int warp_n = wid >> 2;

    const float* rmwsrc = nullptr;
    if (EPI == EPI_DA1) rmwsrc = g_a1;
    else if (EPI == EPI_H2 && KMODE != 0) rmwsrc = g_Sf;
    else if (EPI == EPI_YUPD) rmwsrc = g_Y;

    if (tid < BN) {
        float b = bias ? bias[n0 + tid] : 0.0f;
        sbias[tid] = (EPI == EPI_YUPD) ? b * (float)Kk : b;
    }
    if (EPI == EPI_DA1 || EPI == EPI_YUPD) {
        int t2 = tid - 64;
        if (t2 >= 0 && t2 < BM)
            sdt[t2] = __ldg(dtv + ((m0 + t2) & (Bb - 1))) * (1.0f / Kk);
    }

    const int l_row = tid >> 4;
    const int l_c16 = tid & 15;

    auto issueB = [&](int c) {
        const int k0 = c * BK;
        const uint32_t sb = smem_base + (uint32_t)(c % NSTAGE) * STAGE_BYTES;
#pragma unroll
        for (int i = 0; i < 2; i++) {
            const int row = l_row + i * 32;
            const uint32_t dr = sb + PLANE + (uint32_t)row * ROWB;
            const __half* gr = Bm + (size_t)(n0 + row) * ldb + k0;
#pragma unroll
            for (int j = 0; j < 2; j++) {
                const int cc = l_c16 + j * 16;
                cp16(dr + cc*16, gr + cc*8);
            }
        }
        asm volatile("cp.async.commit_group;");
    };
    auto issueA = [&](int c) {
        const int k0 = c * BK;
        const uint32_t sb = smem_base + (uint32_t)(c % NSTAGE) * STAGE_BYTES;
#pragma unroll
        for (int i = 0; i < 2; i++) {
            const int row = l_row + i * 32;
            const uint32_t dr = sb + (uint32_t)row * ROWB;
            const __half* gr = A + (size_t)(m0 + row) * lda + k0;
#pragma unroll
            for (int j = 0; j < 2; j++) {
                const int cc = l_c16 + j * 16;
                cp16(dr + cc*16, gr + cc*8);
            }
        }
        asm volatile("cp.async.commit_group;");
    };
    auto issueS = [&](int c) {
        const int k0 = c * BK;
        const uint32_t sb = smem_base + (uint32_t)(c % NSTAGE) * STAGE_BYTES;
#pragma unroll
        for (int i = 0; i < 2; i++) {
            const int row = l_row + i * 32;
            const uint32_t dr = sb + (uint32_t)row * ROWB;
            const __half* ga = A  + (size_t)(m0 + row) * lda + k0;
            const __half* gb = Bm + (size_t)(n0 + row) * ldb + k0;
#pragma unroll
            for (int j = 0; j < 2; j++) {
                const int cc = l_c16 + j * 16;
                cp16(dr + cc*16,         ga + cc*8);
                cp16(dr + PLANE + cc*16, gb + cc*8);
            }
        }
        asm volatile("cp.async.commit_group;");
    };

    float acc[2][4];
#pragma unroll
    for (int nj = 0; nj < 2; nj++)
#pragma unroll
        for (int e = 0; e < 4; e++) acc[nj][e] = 0.0f;

    const int nc = Kd / BK;

    // G0: B chunk 0 + epilogue-RMW prefetch (stale data)
    {
        const uint32_t sb = smem_base;
#pragma unroll
        for (int i = 0; i < 2; i++) {
            const int row = l_row + i * 32;
            const uint32_t dr = sb + PLANE + (uint32_t)row * ROWB;
            const __half* gr = Bm + (size_t)(n0 + row) * ldb;
#pragma unroll
            for (int j = 0; j < 2; j++) {
                const int cc = l_c16 + j * 16;
                cp16(dr + cc*16, gr + cc*8);
            }
        }
        if (rmwsrc) {
#pragma unroll
            for (int j = 0; j < 2; j++) {
                const int u = tid + j * 512;
                const int row = u >> 4, ch = u & 15;
                cp16(smem_base + RMW_OFF + row*256 + ch*16,
                     rmwsrc + (size_t)(m0 + row) * ldc + n0 + ch*4);
            }
        }
        asm volatile("cp.async.commit_group;");
    }
    issueB(1); issueB(2);
    cudaGridDependencySynchronize();
    issueA(0); issueA(1); issueA(2);

    const int arow = lane & 15, acol8 = (lane >> 4) * 8;
    const int brow = ((lane >> 4) & 1) * 8 + (lane & 7);
    const int bcol8 = ((lane >> 3) & 1) * 8;
    const uint32_t aoff = (uint32_t)(warp_m*16 + arow) * ROWB + acol8 * 2;
    const uint32_t boff = PLANE + (uint32_t)(warp_n*16 + brow) * ROWB + bcol8 * 2;

    for (int c = 0; c < nc; c++) {
        if (c == 0)          { asm volatile("cp.async.wait_group 2;"); }
        else if (c + 1 < nc) { asm volatile("cp.async.wait_group 1;"); }
        else                 { asm volatile("cp.async.wait_group 0;"); }
        __syncthreads();
        if (c == 1 && nc == 4) issueS(3);

        const uint32_t sb = smem_base + (uint32_t)(c % NSTAGE) * STAGE_BYTES;
        uint32_t ah[2][4], bf[2][4];
        ldm_x4(sb + aoff, ah[0]);
        ldm_x4(sb + boff, bf[0]);
#pragma unroll
        for (int kk = 0; kk < 16; kk++) {
            const int cur = kk & 1, nxt = cur ^ 1;
            if (kk < 15) {
                ldm_x4(sb + aoff + (kk+1)*32, ah[nxt]);
                ldm_x4(sb + boff + (kk+1)*32, bf[nxt]);
            }
            mma16816(acc[0], ah[cur], bf[cur][0], bf[cur][1]);
            mma16816(acc[1], ah[cur], bf[cur][2], bf[cur][3]);
        }
    }

    cudaTriggerProgrammaticLaunchCompletion();

    const float* rmws = (const float*)(smem + RMW_OFF);
    const int rbase = lane >> 2;
    const int cb2 = (lane & 3) * 2;
#pragma unroll
    for (int nj = 0; nj < 2; nj++) {
#pragma unroll
        for (int half = 0; half < 2; half++) {
            const int ml = warp_m*16 + rbase + half*8;
            const int m  = m0 + ml;
            const int nl = warp_n*16 + nj*8 + cb2;
            float v0 = acc[nj][half*2 + 0] + sbias[nl];
            float v1 = acc[nj][half*2 + 1] + sbias[nl + 1];
            const size_t o = (size_t)m * ldc + n0 + nl;
            if (EPI == EPI_A1) {
                g_a1[o] = v0; g_a1[o+1] = v1;
                *(__half2*)(g_h1h + o) = __floats2half2_rn(tanhf(v0), tanhf(v1));
            } else if (EPI == EPI_H2) {
                v0 = tanhf(v0); v1 = tanhf(v1);
                *(__half2*)(g_h2h + o) = __floats2half2_rn(v0, v1);
                float s0, s1;
                if (KMODE == 0) { s0 = v0; s1 = v1; }
                else {
                    float2 sp = *(const float2*)(rmws + ml*64 + nl);
                    s0 = sp.x + v0; s1 = sp.y + v1;
                }
                g_Sf[o] = s0; g_Sf[o+1] = s1;
                if (KMODE == 2)
                    *(__half2*)(g_Sh + o) = __floats2half2_rn(s0, s1);
            } else if (EPI == EPI_DA1) {
                const float sub = sdt[ml];
                float2 ap = *(const float2*)(rmws + ml*64 + nl);
                float a0 = ap.x + sub * v0;
                float a1v = ap.y + sub * v1;
                g_a1[o] = a0; g_a1[o+1] = a1v;
                *(__half2*)(g_h1h + o) = __floats2half2_rn(tanhf(a0), tanhf(a1v));
            } else if (EPI == EPI_YUPD) {
                const float sub = sdt[ml];
                float2 yp = *(const float2*)(rmws + ml*64 + nl);
                float y0 = yp.x + sub * v0;
                float y1 = yp.y + sub * v1;
                g_Y[o] = y0; g_Y[o+1] = y1;
                *(__half2*)(g_Yh + o) = __floats2half2_rn(y0, y1);
            } else if (EPI == EPI_LRELU) {
                v0 = (v0 > 0.f) ? v0 : 0.1f*v0;
                v1 = (v1 > 0.f) ? v1 : 0.1f*v1;
                *(float2*)(Cf + o) = make_float2(v0, v1);
            } else {
                *(float2*)(Cf + o) = make_float2(v0, v1);
            }
        }
    }
}

// ---------------- merged H2+DA1 kernel with 16-CTA row barrier ----------------
// KM: 0 -> k==0 (Sf init), 1 -> k in 1..6 (Sf accumulate)
template<int KM>
__global__ void __launch_bounds__(NTHR)
k_hd(const float* __restrict__ b1, const float* __restrict__ dtv, int target)
{
    extern __shared__ char smem[];
    __shared__ float sb1[BN];
    __shared__ float sc0[BN];
    __shared__ float sdt[BM];
    const uint32_t smem_base = smem_u32(smem);
    const int tid = threadIdx.x;
    const int wid = tid >> 5, lane = tid & 31;
    const int warp_m = wid & 3, warp_n = wid >> 2;
    const int m0 = blockIdx.y << 6, n0 = blockIdx.x << 6;

    if (tid < BN) sb1[tid] = b1[n0 + tid];
    else if (tid < 2*BN) sc0[tid - BN] = g_c0[n0 + tid - BN];
    else if (tid < 2*BN + BM)
        sdt[tid - 2*BN] = __ldg(dtv + ((m0 + tid - 2*BN) & (Bb - 1))) * (1.0f / Kk);

    const int l_row = tid >> 4;
    const int l_c16 = tid & 15;

    auto issueB = [&](const __half* W, int c) {
        const int k0 = c * BK;
        const uint32_t sb = smem_base + (uint32_t)(c % NSTAGE) * STAGE_BYTES;
#pragma unroll
        for (int i = 0; i < 2; i++) {
            const int row = l_row + i * 32;
            const uint32_t dr = sb + PLANE + (uint32_t)row * ROWB;
            const __half* gr = W + (size_t)(n0 + row) * Hh + k0;
#pragma unroll
            for (int j = 0; j < 2; j++) {
                const int cc = l_c16 + j * 16;
                cp16(dr + cc*16, gr + cc*8);
            }
        }
        asm volatile("cp.async.commit_group;");
    };
    auto issueA = [&](const __half* Am, int c) {
        const int k0 = c * BK;
        const uint32_t sb = smem_base + (uint32_t)(c % NSTAGE) * STAGE_BYTES;
#pragma unroll
        for (int i = 0; i < 2; i++) {
            const int row = l_row + i * 32;
            const uint32_t dr = sb + (uint32_t)row * ROWB;
            const __half* gr = Am + (size_t)(m0 + row) * Hh + k0;
#pragma unroll
            for (int j = 0; j < 2; j++) {
                const int cc = l_c16 + j * 16;
                cp16(dr + cc*16, gr + cc*8);
            }
        }
        asm volatile("cp.async.commit_group;");
    };
    auto issueS = [&](const __half* Am, const __half* W, int c) {
        const int k0 = c * BK;
        const uint32_t sb = smem_base + (uint32_t)(c % NSTAGE) * STAGE_BYTES;
#pragma unroll
        for (int i = 0; i < 2; i++) {
            const int row = l_row + i * 32;
            const uint32_t dr = sb + (uint32_t)row * ROWB;
            const __half* ga = Am + (size_t)(m0 + row) * Hh + k0;
            const __half* gb = W  + (size_t)(n0 + row) * Hh + k0;
#pragma unroll
            for (int j = 0; j < 2; j++) {
                const int cc = l_c16 + j * 16;
                cp16(dr + cc*16,         ga + cc*8);
                cp16(dr + PLANE + cc*16, gb + cc*8);
            }
        }
        asm volatile("cp.async.commit_group;");
    };

    const int arow = lane & 15, acol8 = (lane >> 4) * 8;
    const int brow = ((lane >> 4) & 1) * 8 + (lane & 7);
    const int bcol8 = ((lane >> 3) & 1) * 8;
    const uint32_t aoff = (uint32_t)(warp_m*16 + arow) * ROWB + acol8 * 2;
    const uint32_t boff = PLANE + (uint32_t)(warp_n*16 + brow) * ROWB + bcol8 * 2;

    auto kloop = [&](const __half* Am, const __half* W, float acc[2][4]) {
#pragma unroll 1
        for (int c = 0; c < 4; c++) {
            if (c == 0)      { asm volatile("cp.async.wait_group 2;"); }
            else if (c < 3)  { asm volatile("cp.async.wait_group 1;"); }
            else             { asm volatile("cp.async.wait_group 0;"); }
            __syncthreads();
            if (c == 1) issueS(Am, W, 3);
            const uint32_t sb = smem_base + (uint32_t)(c % NSTAGE) * STAGE_BYTES;
            uint32_t ah[2][4], bf[2][4];
            ldm_x4(sb + aoff, ah[0]);
            ldm_x4(sb + boff, bf[0]);
#pragma unroll
            for (int kk = 0; kk < 16; kk++) {
                const int cur = kk & 1, nxt = cur ^ 1;
                if (kk < 15) {
                    ldm_x4(sb + aoff + (kk+1)*32, ah[nxt]);
                    ldm_x4(sb + boff + (kk+1)*32, bf[nxt]);
                }
                mma16816(acc[0], ah[cur], bf[cur][0], bf[cur][1]);
                mma16816(acc[1], ah[cur], bf[cur][2], bf[cur][3]);
            }
        }
    };

    // ---- phase 1 prologue ----
    issueB(g_W1h, 0); issueB(g_W1h, 1); issueB(g_W1h, 2);
    cudaGridDependencySynchronize();

    const int rbase = lane >> 2, cb2 = (lane & 3) * 2;
    float2 sfr[2][2], a1r[2][2];
#pragma unroll
    for (int nj = 0; nj < 2; nj++)
#pragma unroll
        for (int half = 0; half < 2; half++) {
            const int ml = warp_m*16 + rbase + half*8;
            const int nl = warp_n*16 + nj*8 + cb2;
            const size_t o = (size_t)(m0 + ml) * Hh + n0 + nl;
            if (KM == 1) sfr[nj][half] = *(const float2*)(g_Sf + o);
            a1r[nj][half] = *(const float2*)(g_a1 + o);
        }

    issueA(g_h1h, 0); issueA(g_h1h, 1); issueA(g_h1h, 2);

    float acc[2][4];
#pragma unroll
    for (int nj = 0; nj < 2; nj++)
#pragma unroll
        for (int e = 0; e < 4; e++) acc[nj][e] = 0.0f;

    kloop(g_h1h, g_W1h, acc);

    // ---- phase 1 epilogue: h2 = tanh(.+b1); Sf (+)= h2 ----
#pragma unroll
    for (int nj = 0; nj < 2; nj++)
#pragma unroll
        for (int half = 0; half < 2; half++) {
            const int ml = warp_m*16 + rbase + half*8;
            const int nl = warp_n*16 + nj*8 + cb2;
            const size_t o = (size_t)(m0 + ml) * Hh + n0 + nl;
            float v0 = tanhf(acc[nj][half*2 + 0] + sb1[nl]);
            float v1 = tanhf(acc[nj][half*2 + 1] + sb1[nl + 1]);
            *(__half2*)(g_h2h + o) = __floats2half2_rn(v0, v1);
            float s0 = v0, s1 = v1;
            if (KM == 1) { s0 += sfr[nj][half].x; s1 += sfr[nj][half].y; }
            *(float2*)(g_Sf + o) = make_float2(s0, s1);
        }

    // ---- row barrier (16 CTAs of this row-block) ----
    __syncthreads();                        // all phase-1 reads/stores done
    issueB(g_W20h, 0); issueB(g_W20h, 1); issueB(g_W20h, 2);  // overlap spin
    if (tid == 0) {
        __threadfence();
        atomicAdd(&g_rowcnt[blockIdx.y], 1u);
        unsigned v;
        do {
            asm volatile("ld.acquire.gpu.u32 %0, [%1];"
                         : "=r"(v) : "l"(&g_rowcnt[blockIdx.y]) : "memory");
        } while (v < (unsigned)target);
    }
    __syncthreads();

    // ---- phase 2: a1 += sub*(h2 @ W20^T + c0); h1 = tanh(a1) ----
    issueA(g_h2h, 0); issueA(g_h2h, 1); issueA(g_h2h, 2);
#pragma unroll
    for (int nj = 0; nj < 2; nj++)
#pragma unroll
        for (int e = 0; e < 4; e++) acc[nj][e] = 0.0f;

    kloop(g_h2h, g_W20h, acc);

    cudaTriggerProgrammaticLaunchCompletion();

#pragma unroll
    for (int nj = 0; nj < 2; nj++)
#pragma unroll
        for (int half = 0; half < 2; half++) {
            const int ml = warp_m*16 + rbase + half*8;
            const int nl = warp_n*16 + nj*8 + cb2;
            const size_t o = (size_t)(m0 + ml) * Hh + n0 + nl;
            const float sub = sdt[ml];
            float a0  = a1r[nj][half].x + sub * (acc[nj][half*2 + 0] + sc0[nl]);
            float a1v = a1r[nj][half].y + sub * (acc[nj][half*2 + 1] + sc0[nl + 1]);
            *(float2*)(g_a1 + o) = make_float2(a0, a1v);
            *(__half2*)(g_h1h + o) = __floats2half2_rn(tanhf(a0), tanhf(a1v));
        }
}

// ---------------- kernels on top of the standalone core ----------------
template<int EPI, int KMODE = 0>
__global__ void __launch_bounds__(NTHR)
k_mgemm(const __half* __restrict__ A, int lda,
        const __half* __restrict__ Bm, int ldb,
        const float* __restrict__ bias,
        float* __restrict__ Cf, int ldc, int Kd,
        const float* __restrict__ dtv)
{
    gemm_core<EPI, KMODE>(A, lda, Bm, ldb, bias, blockIdx.y*64, blockIdx.x*64,
                          Kd, Cf, ldc, dtv);
}

__global__ void __launch_bounds__(NTHR)
k_gh0(const float* __restrict__ gbh)
{
    gemm_core<EPI_STORE, 0>(g_Yh, Ff, g_Whh, Ff, gbh,
                            blockIdx.y*64, blockIdx.x*64, Ff,
                            g_gh, G3F, nullptr);
}

__global__ void __launch_bounds__(NTHR)
k_gxgh1(const float* __restrict__ gbx, const float* __restrict__ gbh)
{
    if (blockIdx.z == 0)
        gemm_core<EPI_STORE, 0>(g_x1h, Ff, g_Wxh + (size_t)G3F*Ff, Ff, gbx + G3F,
                                blockIdx.y*64, blockIdx.x*64, Ff,
                                g_gx1, G3F, nullptr);
    else
        gemm_core<EPI_STORE, 0>(g_Yh + (size_t)Bb*Ff, Ff, g_Whh + (size_t)G3F*Ff, Ff,
                                gbh + G3F,
                                blockIdx.y*64, blockIdx.x*64, Ff,
                                g_gh + (size_t)Bb*G3F, G3F, nullptr);
}

__global__ void k_gru(const float* __restrict__ gx, const float* __restrict__ gh,
                      float* __restrict__ h, __half* __restrict__ hh,
                      __half* __restrict__ xh)
{
    cudaGridDependencySynchronize();
    int idx = blockIdx.x*blockDim.x + threadIdx.x;
    if (idx >= Bb*Ff) return;
    int b = idx / Ff, f = idx % Ff;
    int o = b*G3F + f;
    float r  = 1.0f / (1.0f + expf(-(gx[o]        + gh[o]       )));
    float z  = 1.0f / (1.0f + expf(-(gx[o + Ff]   + gh[o + Ff]  )));
    float n  = tanhf(gx[o + 2*Ff] + r * gh[o + 2*Ff]);
    float hn = (1.0f - z) * n + z * h[idx];
    h[idx] = hn;
    __half hv = __float2half_rn(hn);
    hh[idx] = hv;
    xh[idx] = hv;
}

__global__ void k_a1init(const float* __restrict__ b0) {
    int stride = gridDim.x * blockDim.x;
    for (int i = blockIdx.x*blockDim.x + threadIdx.x; i < MB*Hh; i += stride) {
        float v = b0[i & (Hh - 1)];
        g_a1[i] = v;
        g_h1h[i] = __float2half_rn(tanhf(v));
    }
}

__global__ void k_cvt_all(const float* __restrict__ W0, const float* __restrict__ W1,
                          const float* __restrict__ W2o, const float* __restrict__ gWx,
                          const float* __restrict__ gWh, const float* __restrict__ rW1)
{
    const int n0 = Hh*Ff, n1 = n0 + Hh*Hh, n2 = n1 + Ff*Hh;
    const int n3 = n2 + Ll*G3F*Ff, n4 = n3 + Ll*G3F*Ff, n5 = n4 + 128*Ff;
    int stride = gridDim.x * blockDim.x;
    for (int i = blockIdx.x*blockDim.x + threadIdx.x; i < n5; i += stride) {
        float v; __half* d;
        if      (i < n0) { v = W0[i];        d = g_W0h  + i; }
        else if (i < n1) { v = W1[i - n0];   d = g_W1h  + (i - n0); }
        else if (i < n2) { v = W2o[i - n1];  d = g_W2h  + (i - n1); }
        else if (i < n3) { v = gWx[i - n2];  d = g_Wxh  + (i - n2); }
        else if (i < n4) { v = gWh[i - n3];  d = g_Whh  + (i - n3); }
        else             { v = rW1[i - n4];  d = g_rW1h + (i - n4); }
        *d = __float2half_rn(v);
    }
}

__global__ void k_cvt(const float* __restrict__ src, __half* __restrict__ dst, int n) {
    int stride = gridDim.x * blockDim.x;
    for (int i = blockIdx.x*blockDim.x + threadIdx.x; i < n; i += stride)
        dst[i] = __float2half_rn(src[i]);
}

__global__ void k_transpose(const float* __restrict__ src, __half* __restrict__ dst,
                            int R, int C) {
    int stride = gridDim.x * blockDim.x;
    for (int i = blockIdx.x*blockDim.x + threadIdx.x; i < R*C; i += stride) {
        int cc = i / R, rr = i % R;
        dst[(size_t)cc*R + rr] = __float2half_rn(src[(size_t)rr*C + cc]);
    }
}

__global__ void k_c0(const float* __restrict__ W0, const float* __restrict__ b2) {
    int i = blockIdx.x*blockDim.x + threadIdx.x;
    if (i >= Hh) return;
    const float* row = W0 + (size_t)i*Ff;
    float acc = 0.0f;
#pragma unroll 8
    for (int f = 0; f < Ff; f++) acc += row[f] * b2[f];
    g_c0[i] = acc;
}

__global__ void k_prep_x(const float* __restrict__ fv, const float* __restrict__ fi) {
    int stride = gridDim.x * blockDim.x;
    int total = Ss*Bb*Ff;
    for (int idx = blockIdx.x*blockDim.x + threadIdx.x; idx < total; idx += stride) {
        int f = idx % Ff;
        int sb = idx / Ff;
        int b = sb % Bb, s = sb / Bb;
        float v = (f < VFd) ? fv[(b*Ss + s)*VFd + f] : fi[(b*Ss + s)*IFd + (f - VFd)];
        g_xh[idx] = __float2half_rn(v);
    }
}

__global__ void k_prep_misc(const float* __restrict__ ts) {
    int stride = gridDim.x * blockDim.x;
    int gtid = blockIdx.x*blockDim.x + threadIdx.x;
    for (int i = gtid; i < MB*Ff; i += stride) {
        g_Y[i] = 0.0f; g_Yh[i] = __float2half(0.0f);
    }
    for (int i = gtid; i < Ss*Bb; i += stride) {
        int s = i / Bb, b = i % Bb;
        g_dt[i] = (s < Ss-1) ? (ts[b*Ss + s + 1] - ts[b*Ss + s]) : 0.0f;
    }
    if (gtid < 8) g_rowcnt[gtid] = 0u;
}

__global__ void k_pose(const float* __restrict__ W2, const float* __restrict__ b2,
                       float* __restrict__ outp)
{
    int idx = blockIdx.x*blockDim.x + threadIdx.x;
    if (idx >= Ss*Bb*6) return;
    int n = idx % 6;
    int m = idx / 6;
    int b = m % Bb, s = m / Bb;
    const float* hrow = g_hid + (size_t)m * 128;
    const float* wrow = W2 + n * 128;
    float acc = b2[n];
#pragma unroll 8
    for (int k = 0; k < 128; k++) acc += hrow[k] * wrow[k];
    outp[(b*Ss + s)*6 + n] = acc;
}

__global__ void k_copyY(float* __restrict__ outp) {
    int stride = gridDim.x * blockDim.x;
    for (int i = blockIdx.x*blockDim.x + threadIdx.x; i < MB*Ff; i += stride)
        outp[i] = g_Y[i];
}

// ---------------- PDL launch helper ----------------
template<typename F, typename... Args>
static inline void pdl(F f, dim3 grid, int block, size_t shm, Args... args) {
    cudaLaunchConfig_t cfg = {};
    cfg.gridDim = grid;
    cfg.blockDim = dim3((unsigned)block, 1, 1);
    cfg.dynamicSmemBytes = shm;
    cfg.stream = 0;
    cudaLaunchAttribute at[1];
    at[0].id = cudaLaunchAttributeProgrammaticStreamSerialization;
    at[0].val.programmaticStreamSerializationAllowed = 1;
    cfg.attrs = at;
    cfg.numAttrs = 1;
    cudaLaunchKernelEx(&cfg, f, args...);
}

extern "C" void kernel_launch(void* const* d_in, const int* in_sizes, int n_in,
                              void* d_out, int out_size)
{
    const float* fv  = (const float*)d_in[0];
    const float* fi  = (const float*)d_in[1];
    const float* ts  = (const float*)d_in[2];
    const float* W0  = (const float*)d_in[3];
    const float* b0  = (const float*)d_in[4];
    const float* W1  = (const float*)d_in[5];
    const float* b1  = (const float*)d_in[6];
    const float* W2o = (const float*)d_in[7];
    const float* b2o = (const float*)d_in[8];
    const float* gWx = (const float*)d_in[9];
    const float* gWh = (const float*)d_in[10];
    const float* gbx = (const float*)d_in[11];
    const float* gbh = (const float*)d_in[12];
    const float* rW1 = (const float*)d_in[13];
    const float* rb1 = (const float*)d_in[14];
    const float* rW2 = (const float*)d_in[15];
    const float* rb2 = (const float*)d_in[16];

#define SETSMEM(K) cudaFuncSetAttribute(K, cudaFuncAttributeMaxDynamicSharedMemorySize, SMEM_TOTAL)
    SETSMEM((k_mgemm<EPI_STORE, 0>)); SETSMEM((k_mgemm<EPI_LRELU, 0>));
    SETSMEM((k_mgemm<EPI_A1, 0>));    SETSMEM((k_mgemm<EPI_YUPD, 0>));
    SETSMEM((k_mgemm<EPI_H2, 0>));    SETSMEM((k_mgemm<EPI_H2, 2>));
    SETSMEM(k_gh0); SETSMEM(k_gxgh1);
    SETSMEM(k_hd<0>); SETSMEM(k_hd<1>);
#undef SETSMEM

#define SYM(p, s) float* p; cudaGetSymbolAddress((void**)&p, s)
#define SYMH(p, s) __half* p; cudaGetSymbolAddress((void**)&p, s)
    SYM(pdt, g_dt); SYM(pgx0, g_gx0); SYM(pgx1, g_gx1); SYM(pgh, g_gh);
    SYM(phid, g_hid); SYM(pW20f, g_W20f); SYM(pc0, g_c0); SYM(pY, g_Y);
    SYMH(pxh, g_xh); SYMH(pouth, g_outh); SYMH(pYh, g_Yh);
    SYMH(ph1h, g_h1h); SYMH(ph2h, g_h2h); SYMH(pSh, g_Sh); SYMH(px1h, g_x1h);
    SYMH(pW0h, g_W0h); SYMH(pW1h, g_W1h); SYMH(pW2h, g_W2h);
    SYMH(pW2Th, g_W2Th); SYMH(pW20h, g_W20h);
    SYMH(pWxh, g_Wxh); SYMH(pWhh, g_Whh); SYMH(prW1, g_rW1h);
#undef SYM
#undef SYMH

    k_cvt_all<<<1024, 256>>>(W0, W1, W2o, gWx, gWh, rW1);
    k_transpose<<<512, 256>>>(W2o, pW2Th, Ff, Hh);
    k_c0<<<(Hh + 255)/256, 256>>>(W0, b2o);
    pdl(k_mgemm<EPI_STORE, 0>, dim3(Hh/BN, Hh/BM), NTHR, (size_t)SMEM_TOTAL,
        (const __half*)pW0h, (int)Ff, (const __half*)pW2Th, (int)Ff,
        (const float*)nullptr, pW20f, (int)Hh, (int)Ff, (const float*)nullptr);
    k_cvt<<<512, 256>>>(pW20f, pW20h, Hh*Hh);

    k_prep_x<<<512, 256>>>(fv, fi);
    k_prep_misc<<<512, 256>>>(ts);

    pdl(k_mgemm<EPI_STORE, 0>, dim3(G3F/BN, (Ss*Bb)/BM), NTHR, (size_t)SMEM_TOTAL,
        (const __half*)pxh, (int)Ff, (const __half*)pWxh, (int)Ff,
        gbx, pgx0, (int)G3F, (int)Ff, (const float*)nullptr);

    const int gruBlocks = (Bb*Ff + 255) / 256;
    const dim3 gridH(Hh/BN, MB/BM);     // 16 x 8 = 128
    const dim3 gridYU(Ff/BN, MB/BM);
    const dim3 gridG(G3F/BN, Bb/BM);

    int epoch = 0;
    for (int t = 0; t < Ss; t++) {
        const float* dtv = pdt + t*Bb;
        if (t < Ss - 1) {
            if (t == 0)
                k_a1init<<<512, 256>>>(b0);
            else
                pdl(k_mgemm<EPI_A1, 0>, gridH, NTHR, (size_t)SMEM_TOTAL,
                    (const __half*)pYh, (int)Ff, (const __half*)pW0h, (int)Ff,
                    b0, (float*)nullptr, (int)Hh, (int)Ff, (const float*)nullptr);
            // merged H2+DA1 pairs for k = 0..6
            for (int k = 0; k < Kk - 1; k++) {
                ++epoch;
                if (k == 0)
                    pdl(k_hd<0>, gridH, NTHR, (size_t)SMEM_TOTAL, b1, dtv, epoch*16);
                else
                    pdl(k_hd<1>, gridH, NTHR, (size_t)SMEM_TOTAL, b1, dtv, epoch*16);
            }
            // final H2 (k = 7): accumulates Sf and emits Sh
            pdl(k_mgemm<EPI_H2, 2>, gridH, NTHR, (size_t)SMEM_TOTAL,
                (const __half*)ph1h, (int)Hh, (const __half*)pW1h, (int)Hh,
                b1, (float*)nullptr, (int)Hh, (int)Hh, (const float*)nullptr);
            pdl(k_mgemm<EPI_YUPD, 0>, gridYU, NTHR, (size_t)SMEM_TOTAL,
                (const __half*)pSh, (int)Hh, (const __half*)pW2h, (int)Hh,
                b2o, (float*)nullptr, (int)Ff, (int)Hh, dtv);
        }
        pdl(k_gh0, gridG, NTHR, (size_t)SMEM_TOTAL, gbh);
        pdl(k_gru, dim3(gruBlocks), 256, (size_t)0,
            (const float*)(pgx0 + (size_t)t*Bb*G3F), (const float*)pgh,
            pY, pYh, px1h);
        pdl(k_gxgh1, dim3(G3F/BN, Bb/BM, 2), NTHR, (size_t)SMEM_TOTAL, gbx, gbh);
        pdl(k_gru, dim3(gruBlocks), 256, (size_t)0,
            (const float*)pgx1, (const float*)(pgh + (size_t)Bb*G3F),
            pY + Bb*Ff, pYh + Bb*Ff, pouth + (size_t)t*Bb*Ff);
    }

    pdl(k_mgemm<EPI_LRELU, 0>, dim3(128/BN, (Ss*Bb)/BM), NTHR, (size_t)SMEM_TOTAL,
        (const __half*)pouth, (int)Ff, (const __half*)prW1, (int)Ff,
        rb1, phid, (int)128, (int)Ff, (const float*)nullptr);
    k_pose<<<(Ss*Bb*6 + 127)/128, 128>>>(rW2, rb2, (float*)d_out);

    if (out_size >= Ss*Bb*6 + MB*Ff)
        k_copyY<<<768, 256>>>((float*)d_out + Ss*Bb*6);
}

// round 16
// speedup vs baseline: 1.0648x; 1.0648x over previous
#include <cuda_runtime.h>
#include <cuda_fp16.h>
#include <math.h>
#include <stdint.h>

#define Bb   256
#define Ss   32
#define VFd  512
#define IFd  256
#define Ff   768
#define Hh   1024
#define Ll   2
#define Kk   8
#define MB   (Ll*Bb)
#define G3F  (3*Ff)

#define BM 64
#define BN 64
#define BK 256
#define NTHR 512
#define ROWB   528
#define PLANE  (64*ROWB)       // 33792
#define STAGE_BYTES (2*PLANE)  // 67584
#define NSTAGE 3
#define RMW_OFF (NSTAGE*STAGE_BYTES)            // 202752
#define SMEM_TOTAL (NSTAGE*STAGE_BYTES + 16384) // 219136

__device__ __align__(16) float  g_dt  [Ss*Bb];
__device__ __align__(16) float  g_Y   [MB*Ff];
__device__ __align__(16) __half g_Yh  [MB*Ff];
__device__ __align__(16) __half g_xh  [Ss*Bb*Ff];
__device__ __align__(16) float  g_a1  [MB*Hh];
__device__ __align__(16) __half g_h1h [MB*Hh];
__device__ __align__(16) __half g_h2h [MB*Hh];
__device__ __align__(16) float  g_Sf  [MB*Hh];
__device__ __align__(16) __half g_Sh  [MB*Hh];
__device__ __align__(16) __half g_x1h [Bb*Ff];
__device__ __align__(16) __half g_outh[Ss*Bb*Ff];
__device__ __align__(16) float  g_gx0 [Ss*Bb*G3F];
__device__ __align__(16) float  g_gh  [2*Bb*G3F];
__device__ __align__(16) float  g_gx1 [Bb*G3F];
__device__ __align__(16) float  g_hid [Ss*Bb*128];
__device__ __align__(16) float  g_c0  [Hh];
__device__ __align__(16) __half g_W0h [Hh*Ff];
__device__ __align__(16) __half g_W1h [Hh*Hh];
__device__ __align__(16) __half g_W2h [Ff*Hh];
__device__ __align__(16) __half g_W2Th[Hh*Ff];
__device__ __align__(16) float  g_W20f[Hh*Hh];
__device__ __align__(16) __half g_W20h[Hh*Hh];
__device__ __align__(16) __half g_Wxh [Ll*G3F*Ff];
__device__ __align__(16) __half g_Whh [Ll*G3F*Ff];
__device__ __align__(16) __half g_rW1h[128*Ff];

__device__ __forceinline__ uint32_t smem_u32(const void* p) {
    uint32_t a;
    asm("{ .reg .u64 t; cvta.to.shared.u64 t, %1; cvt.u32.u64 %0, t; }" : "=r"(a) : "l"(p));
    return a;
}
__device__ __forceinline__ void cp16(uint32_t dst, const void* src) {
    asm volatile("cp.async.cg.shared.global [%0], [%1], 16;" :: "r"(dst), "l"(src));
}
__device__ __forceinline__ void ldm_x4(uint32_t addr, uint32_t r[4]) {
    asm volatile("ldmatrix.sync.aligned.m8n8.x4.shared.b16 {%0,%1,%2,%3}, [%4];"
                 : "=r"(r[0]), "=r"(r[1]), "=r"(r[2]), "=r"(r[3]) : "r"(addr));
}
__device__ __forceinline__ void mma16816(float d[4], const uint32_t a[4],
                                         uint32_t b0, uint32_t b1) {
    asm volatile("mma.sync.aligned.m16n8k16.row.col.f32.f16.f16.f32 "
                 "{%0,%1,%2,%3}, {%4,%5,%6,%7}, {%8,%9}, {%0,%1,%2,%3};"
                 : "+f"(d[0]), "+f"(d[1]), "+f"(d[2]), "+f"(d[3])
                 : "r"(a[0]), "r"(a[1]), "r"(a[2]), "r"(a[3]), "r"(b0), "r"(b1));
}

enum { EPI_STORE = 0, EPI_LRELU, EPI_A1, EPI_H2, EPI_DA1, EPI_YUPD };

// ---- 64x64 GEMM core: 16 warps as 4(m) x 2(n) x 2(k-split), warp tile 16x32 ----
template<int EPI, int KMODE>
__device__ __forceinline__ void gemm_core(
    const __half* __restrict__ A, int lda,
    const __half* __restrict__ Bm, int ldb,
    const float* __restrict__ bias,
    int m0, int n0, int Kd,
    float* __restrict__ Cf, int ldc,
    const float* __restrict__ dtv)
{
    extern __shared__ char smem[];
    __shared__ float sbias[BN];
    __shared__ float sdt[BM];
    const uint32_t smem_base = smem_u32(smem);
    const int tid = threadIdx.x;
    const int wid = tid >> 5, lane = tid & 31;
    const int warp_k = wid >> 3;        // 0..1
    const int warp_m = (wid >> 1) & 3;  // 0..3 -> 16 rows
    const int warp_n = wid & 1;         // 0..1 -> 32 cols

    const float* rmwsrc = nullptr;
    if (EPI == EPI_DA1) rmwsrc = g_a1;
    else if (EPI == EPI_H2 && KMODE != 0) rmwsrc = g_Sf;
    else if (EPI == EPI_YUPD) rmwsrc = g_Y;

    if (tid < BN) {
        float b = bias ? bias[n0 + tid] : 0.0f;
        sbias[tid] = (EPI == EPI_YUPD) ? b * (float)Kk : b;
    }
    if (EPI == EPI_DA1 || EPI == EPI_YUPD) {
        int t2 = tid - 64;
        if (t2 >= 0 && t2 < BM)
            sdt[t2] = __ldg(dtv + ((m0 + t2) & (Bb - 1))) * (1.0f / Kk);
    }

    const int l_row = tid >> 4;
    const int l_c16 = tid & 15;

    auto issueB = [&](int c) {
        const int k0 = c * BK;
        const uint32_t sb = smem_base + (uint32_t)(c % NSTAGE) * STAGE_BYTES;
#pragma unroll
        for (int i = 0; i < 2; i++) {
            const int row = l_row + i * 32;
            const uint32_t dr = sb + PLANE + (uint32_t)row * ROWB;
            const __half* gr = Bm + (size_t)(n0 + row) * ldb + k0;
#pragma unroll
            for (int j = 0; j < 2; j++) {
                const int cc = l_c16 + j * 16;
                cp16(dr + cc*16, gr + cc*8);
            }
        }
        asm volatile("cp.async.commit_group;");
    };
    auto issueA = [&](int c) {
        const int k0 = c * BK;
        const uint32_t sb = smem_base + (uint32_t)(c % NSTAGE) * STAGE_BYTES;
#pragma unroll
        for (int i = 0; i < 2; i++) {
            const int row = l_row + i * 32;
            const uint32_t dr = sb + (uint32_t)row * ROWB;
            const __half* gr = A + (size_t)(m0 + row) * lda + k0;
#pragma unroll
            for (int j = 0; j < 2; j++) {
                const int cc = l_c16 + j * 16;
                cp16(dr + cc*16, gr + cc*8);
            }
        }
        asm volatile("cp.async.commit_group;");
    };
    auto issueS = [&](int c) {
        const int k0 = c * BK;
        const uint32_t sb = smem_base + (uint32_t)(c % NSTAGE) * STAGE_BYTES;
#pragma unroll
        for (int i = 0; i < 2; i++) {
            const int row = l_row + i * 32;
            const uint32_t dr = sb + (uint32_t)row * ROWB;
            const __half* ga = A  + (size_t)(m0 + row) * lda + k0;
            const __half* gb = Bm + (size_t)(n0 + row) * ldb + k0;
#pragma unroll
            for (int j = 0; j < 2; j++) {
                const int cc = l_c16 + j * 16;
                cp16(dr + cc*16,         ga + cc*8);
                cp16(dr + PLANE + cc*16, gb + cc*8);
            }
        }
        asm volatile("cp.async.commit_group;");
    };

    float acc[4][4];
#pragma unroll
    for (int nj = 0; nj < 4; nj++)
#pragma unroll
        for (int e = 0; e < 4; e++) acc[nj][e] = 0.0f;

    const int nc = Kd / BK;

    // G0: B chunk 0 + epilogue-RMW prefetch (stale data)
    {
        const uint32_t sb = smem_base;
#pragma unroll
        for (int i = 0; i < 2; i++) {
            const int row = l_row + i * 32;
            const uint32_t dr = sb + PLANE + (uint32_t)row * ROWB;
            const __half* gr = Bm + (size_t)(n0 + row) * ldb;
#pragma unroll
            for (int j = 0; j < 2; j++) {
                const int cc = l_c16 + j * 16;
                cp16(dr + cc*16, gr + cc*8);
            }
        }
        if (rmwsrc) {
#pragma unroll
            for (int j = 0; j < 2; j++) {
                const int u = tid + j * 512;
                const int row = u >> 4, ch = u & 15;
                cp16(smem_base + RMW_OFF + row*256 + ch*16,
                     rmwsrc + (size_t)(m0 + row) * ldc + n0 + ch*4);
            }
        }
        asm volatile("cp.async.commit_group;");
    }
    issueB(1); issueB(2);
    cudaGridDependencySynchronize();
    issueA(0); issueA(1); issueA(2);

    const int arow = lane & 15, acol8 = (lane >> 4) * 8;
    const int brow = ((lane >> 4) & 1) * 8 + (lane & 7);
    const int bcol8 = ((lane >> 3) & 1) * 8;
    const uint32_t aoff  = (uint32_t)(warp_m*16 + arow) * ROWB + acol8 * 2
                         + (uint32_t)warp_k * 32;
    const uint32_t boff0 = PLANE + (uint32_t)(warp_n*32 + brow) * ROWB + bcol8 * 2
                         + (uint32_t)warp_k * 32;
    const uint32_t boff1 = boff0 + 16*ROWB;

    for (int c = 0; c < nc; c++) {
        if (c == 0)          { asm volatile("cp.async.wait_group 2;"); }
        else if (c + 1 < nc) { asm volatile("cp.async.wait_group 1;"); }
        else                 { asm volatile("cp.async.wait_group 0;"); }
        __syncthreads();
        if (c == 1 && nc == 4) issueS(3);

        const uint32_t sb = smem_base + (uint32_t)(c % NSTAGE) * STAGE_BYTES;
        // each warp handles kk = 2*s + warp_k, s = 0..7 (byte step 64/s)
        uint32_t ah[2][4], b0f[2][4], b1f[2][4];
        ldm_x4(sb + aoff,  ah[0]);
        ldm_x4(sb + boff0, b0f[0]);
        ldm_x4(sb + boff1, b1f[0]);
#pragma unroll
        for (int s = 0; s < 8; s++) {
            const int cur = s & 1, nxt = cur ^ 1;
            if (s < 7) {
                const uint32_t kb = (uint32_t)(s + 1) * 64;
                ldm_x4(sb + aoff  + kb, ah[nxt]);
                ldm_x4(sb + boff0 + kb, b0f[nxt]);
                ldm_x4(sb + boff1 + kb, b1f[nxt]);
            }
            mma16816(acc[0], ah[cur], b0f[cur][0], b0f[cur][1]);
            mma16816(acc[1], ah[cur], b0f[cur][2], b0f[cur][3]);
            mma16816(acc[2], ah[cur], b1f[cur][0], b1f[cur][1]);
            mma16816(acc[3], ah[cur], b1f[cur][2], b1f[cur][3]);
        }
    }

    cudaTriggerProgrammaticLaunchCompletion();

    // ---- k-split reduction: warp_k=1 stores, warp_k=0 adds ----
    __syncthreads();                 // all MMA smem reads done; stage 0 reusable
    float* red = (float*)smem;       // 8 pairs x 32 lanes x 16 floats = 16 KB
    const int pw = warp_m*2 + warp_n;
    if (warp_k == 1) {
        float4* d = (float4*)(red + (pw*32 + lane)*16);
#pragma unroll
        for (int nj = 0; nj < 4; nj++)
            d[nj] = make_float4(acc[nj][0], acc[nj][1], acc[nj][2], acc[nj][3]);
    }
    __syncthreads();
    if (warp_k == 0) {
        const float4* d = (const float4*)(red + (pw*32 + lane)*16);
#pragma unroll
        for (int nj = 0; nj < 4; nj++) {
            float4 v = d[nj];
            acc[nj][0] += v.x; acc[nj][1] += v.y;
            acc[nj][2] += v.z; acc[nj][3] += v.w;
        }

        const float* rmws = (const float*)(smem + RMW_OFF);
        const int rbase = lane >> 2;
        const int cb2 = (lane & 3) * 2;
#pragma unroll
        for (int nj = 0; nj < 4; nj++) {
#pragma unroll
            for (int half = 0; half < 2; half++) {
                const int ml = warp_m*16 + rbase + half*8;
                const int m  = m0 + ml;
                const int nl = warp_n*32 + nj*8 + cb2;
                float v0 = acc[nj][half*2 + 0] + sbias[nl];
                float v1 = acc[nj][half*2 + 1] + sbias[nl + 1];
                const size_t o = (size_t)m * ldc + n0 + nl;
                if (EPI == EPI_A1) {
                    g_a1[o] = v0; g_a1[o+1] = v1;
                    *(__half2*)(g_h1h + o) = __floats2half2_rn(tanhf(v0), tanhf(v1));
                } else if (EPI == EPI_H2) {
                    v0 = tanhf(v0); v1 = tanhf(v1);
                    *(__half2*)(g_h2h + o) = __floats2half2_rn(v0, v1);
                    float s0, s1;
                    if (KMODE == 0) { s0 = v0; s1 = v1; }
                    else {
                        float2 sp = *(const float2*)(rmws + ml*64 + nl);
                        s0 = sp.x + v0; s1 = sp.y + v1;
                    }
                    g_Sf[o] = s0; g_Sf[o+1] = s1;
                    if (KMODE == 2)
                        *(__half2*)(g_Sh + o) = __floats2half2_rn(s0, s1);
                } else if (EPI == EPI_DA1) {
                    const float sub = sdt[ml];
                    float2 ap = *(const float2*)(rmws + ml*64 + nl);
                    float a0 = ap.x + sub * v0;
                    float a1v = ap.y + sub * v1;
                    g_a1[o] = a0; g_a1[o+1] = a1v;
                    *(__half2*)(g_h1h + o) = __floats2half2_rn(tanhf(a0), tanhf(a1v));
                } else if (EPI == EPI_YUPD) {
                    const float sub = sdt[ml];
                    float2 yp = *(const float2*)(rmws + ml*64 + nl);
                    float y0 = yp.x + sub * v0;
                    float y1 = yp.y + sub * v1;
                    g_Y[o] = y0; g_Y[o+1] = y1;
                    *(__half2*)(g_Yh + o) = __floats2half2_rn(y0, y1);
                } else if (EPI == EPI_LRELU) {
                    v0 = (v0 > 0.f) ? v0 : 0.1f*v0;
                    v1 = (v1 > 0.f) ? v1 : 0.1f*v1;
                    *(float2*)(Cf + o) = make_float2(v0, v1);
                } else {
                    *(float2*)(Cf + o) = make_float2(v0, v1);
                }
            }
        }
    }
}

template<int EPI, int KMODE = 0>
__global__ void __launch_bounds__(NTHR)
k_mgemm(const __half* __restrict__ A, int lda,
        const __half* __restrict__ Bm, int ldb,
        const float* __restrict__ bias,
        float* __restrict__ Cf, int ldc, int Kd,
        const float* __restrict__ dtv)
{
    gemm_core<EPI, KMODE>(A, lda, Bm, ldb, bias, blockIdx.y*64, blockIdx.x*64,
                          Kd, Cf, ldc, dtv);
}

__global__ void __launch_bounds__(NTHR)
k_gh0(const float* __restrict__ gbh)
{
    gemm_core<EPI_STORE, 0>(g_Yh, Ff, g_Whh, Ff, gbh,
                            blockIdx.y*64, blockIdx.x*64, Ff,
                            g_gh, G3F, nullptr);
}

__global__ void __launch_bounds__(NTHR)
k_gxgh1(const float* __restrict__ gbx, const float* __restrict__ gbh)
{
    if (blockIdx.z == 0)
        gemm_core<EPI_STORE, 0>(g_x1h, Ff, g_Wxh + (size_t)G3F*Ff, Ff, gbx + G3F,
                                blockIdx.y*64, blockIdx.x*64, Ff,
                                g_gx1, G3F, nullptr);
    else
        gemm_core<EPI_STORE, 0>(g_Yh + (size_t)Bb*Ff, Ff, g_Whh + (size_t)G3F*Ff, Ff,
                                gbh + G3F,
                                blockIdx.y*64, blockIdx.x*64, Ff,
                                g_gh + (size_t)Bb*G3F, G3F, nullptr);
}

__global__ void k_gru(const float* __restrict__ gx, const float* __restrict__ gh,
                      float* __restrict__ h, __half* __restrict__ hh,
                      __half* __restrict__ xh)
{
    cudaGridDependencySynchronize();
    int idx = blockIdx.x*blockDim.x + threadIdx.x;
    if (idx >= Bb*Ff) return;
    int b = idx / Ff, f = idx % Ff;
    int o = b*G3F + f;
    float r  = 1.0f / (1.0f + expf(-(gx[o]        + gh[o]       )));
    float z  = 1.0f / (1.0f + expf(-(gx[o + Ff]   + gh[o + Ff]  )));
    float n  = tanhf(gx[o + 2*Ff] + r * gh[o + 2*Ff]);
    float hn = (1.0f - z) * n + z * h[idx];
    h[idx] = hn;
    __half hv = __float2half_rn(hn);
    hh[idx] = hv;
    xh[idx] = hv;
}

__global__ void k_a1init(const float* __restrict__ b0) {
    int stride = gridDim.x * blockDim.x;
    for (int i = blockIdx.x*blockDim.x + threadIdx.x; i < MB*Hh; i += stride) {
        float v = b0[i & (Hh - 1)];
        g_a1[i] = v;
        g_h1h[i] = __float2half_rn(tanhf(v));
    }
}

__global__ void k_cvt_all(const float* __restrict__ W0, const float* __restrict__ W1,
                          const float* __restrict__ W2o, const float* __restrict__ gWx,
                          const float* __restrict__ gWh, const float* __restrict__ rW1)
{
    const int n0 = Hh*Ff, n1 = n0 + Hh*Hh, n2 = n1 + Ff*Hh;
    const int n3 = n2 + Ll*G3F*Ff, n4 = n3 + Ll*G3F*Ff, n5 = n4 + 128*Ff;
    int stride = gridDim.x * blockDim.x;
    for (int i = blockIdx.x*blockDim.x + threadIdx.x; i < n5; i += stride) {
        float v; __half* d;
        if      (i < n0) { v = W0[i];        d = g_W0h  + i; }
        else if (i < n1) { v = W1[i - n0];   d = g_W1h  + (i - n0); }
        else if (i < n2) { v = W2o[i - n1];  d = g_W2h  + (i - n1); }
        else if (i < n3) { v = gWx[i - n2];  d = g_Wxh  + (i - n2); }
        else if (i < n4) { v = gWh[i - n3];  d = g_Whh  + (i - n3); }
        else             { v = rW1[i - n4];  d = g_rW1h + (i - n4); }
        *d = __float2half_rn(v);
    }
}

__global__ void k_cvt(const float* __restrict__ src, __half* __restrict__ dst, int n) {
    int stride = gridDim.x * blockDim.x;
    for (int i = blockIdx.x*blockDim.x + threadIdx.x; i < n; i += stride)
        dst[i] = __float2half_rn(src[i]);
}

__global__ void k_transpose(const float* __restrict__ src, __half* __restrict__ dst,
                            int R, int C) {
    int stride = gridDim.x * blockDim.x;
    for (int i = blockIdx.x*blockDim.x + threadIdx.x; i < R*C; i += stride) {
        int cc = i / R, rr = i % R;
        dst[(size_t)cc*R + rr] = __float2half_rn(src[(size_t)rr*C + cc]);
    }
}

__global__ void k_c0(const float* __restrict__ W0, const float* __restrict__ b2) {
    int i = blockIdx.x*blockDim.x + threadIdx.x;
    if (i >= Hh) return;
    const float* row = W0 + (size_t)i*Ff;
    float acc = 0.0f;
#pragma unroll 8
    for (int f = 0; f < Ff; f++) acc += row[f] * b2[f];
    g_c0[i] = acc;
}

__global__ void k_prep_x(const float* __restrict__ fv, const float* __restrict__ fi) {
    int stride = gridDim.x * blockDim.x;
    int total = Ss*Bb*Ff;
    for (int idx = blockIdx.x*blockDim.x + threadIdx.x; idx < total; idx += stride) {
        int f = idx % Ff;
        int sb = idx / Ff;
        int b = sb % Bb, s = sb / Bb;
        float v = (f < VFd) ? fv[(b*Ss + s)*VFd + f] : fi[(b*Ss + s)*IFd + (f - VFd)];
        g_xh[idx] = __float2half_rn(v);
    }
}

__global__ void k_prep_misc(const float* __restrict__ ts) {
    int stride = gridDim.x * blockDim.x;
    int gtid = blockIdx.x*blockDim.x + threadIdx.x;
    for (int i = gtid; i < MB*Ff; i += stride) {
        g_Y[i] = 0.0f; g_Yh[i] = __float2half(0.0f);
    }
    for (int i = gtid; i < Ss*Bb; i += stride) {
        int s = i / Bb, b = i % Bb;
        g_dt[i] = (s < Ss-1) ? (ts[b*Ss + s + 1] - ts[b*Ss + s]) : 0.0f;
    }
}

__global__ void k_pose(const float* __restrict__ W2, const float* __restrict__ b2,
                       float* __restrict__ outp)
{
    int idx = blockIdx.x*blockDim.x + threadIdx.x;
    if (idx >= Ss*Bb*6) return;
    int n = idx % 6;
    int m = idx / 6;
    int b = m % Bb, s = m / Bb;
    const float* hrow = g_hid + (size_t)m * 128;
    const float* wrow = W2 + n * 128;
    float acc = b2[n];
#pragma unroll 8
    for (int k = 0; k < 128; k++) acc += hrow[k] * wrow[k];
    outp[(b*Ss + s)*6 + n] = acc;
}

__global__ void k_copyY(float* __restrict__ outp) {
    int stride = gridDim.x * blockDim.x;
    for (int i = blockIdx.x*blockDim.x + threadIdx.x; i < MB*Ff; i += stride)
        outp[i] = g_Y[i];
}

// ---------------- PDL launch helper ----------------
template<typename F, typename... Args>
static inline void pdl(F f, dim3 grid, int block, size_t shm, Args... args) {
    cudaLaunchConfig_t cfg = {};
    cfg.gridDim = grid;
    cfg.blockDim = dim3((unsigned)block, 1, 1);
    cfg.dynamicSmemBytes = shm;
    cfg.stream = 0;
    cudaLaunchAttribute at[1];
    at[0].id = cudaLaunchAttributeProgrammaticStreamSerialization;
    at[0].val.programmaticStreamSerializationAllowed = 1;
    cfg.attrs = at;
    cfg.numAttrs = 1;
    cudaLaunchKernelEx(&cfg, f, args...);
}

extern "C" void kernel_launch(void* const* d_in, const int* in_sizes, int n_in,
                              void* d_out, int out_size)
{
    const float* fv  = (const float*)d_in[0];
    const float* fi  = (const float*)d_in[1];
    const float* ts  = (const float*)d_in[2];
    const float* W0  = (const float*)d_in[3];
    const float* b0  = (const float*)d_in[4];
    const float* W1  = (const float*)d_in[5];
    const float* b1  = (const float*)d_in[6];
    const float* W2o = (const float*)d_in[7];
    const float* b2o = (const float*)d_in[8];
    const float* gWx = (const float*)d_in[9];
    const float* gWh = (const float*)d_in[10];
    const float* gbx = (const float*)d_in[11];
    const float* gbh = (const float*)d_in[12];
    const float* rW1 = (const float*)d_in[13];
    const float* rb1 = (const float*)d_in[14];
    const float* rW2 = (const float*)d_in[15];
    const float* rb2 = (const float*)d_in[16];

#define SETSMEM(K) cudaFuncSetAttribute(K, cudaFuncAttributeMaxDynamicSharedMemorySize, SMEM_TOTAL)
    SETSMEM((k_mgemm<EPI_STORE, 0>)); SETSMEM((k_mgemm<EPI_LRELU, 0>));
    SETSMEM((k_mgemm<EPI_A1, 0>));    SETSMEM((k_mgemm<EPI_DA1, 0>));
    SETSMEM((k_mgemm<EPI_YUPD, 0>));
    SETSMEM((k_mgemm<EPI_H2, 0>)); SETSMEM((k_mgemm<EPI_H2, 1>)); SETSMEM((k_mgemm<EPI_H2, 2>));
    SETSMEM(k_gh0); SETSMEM(k_gxgh1);
#undef SETSMEM

#define SYM(p, s) float* p; cudaGetSymbolAddress((void**)&p, s)
#define SYMH(p, s) __half* p; cudaGetSymbolAddress((void**)&p, s)
    SYM(pdt, g_dt); SYM(pgx0, g_gx0); SYM(pgx1, g_gx1); SYM(pgh, g_gh);
    SYM(phid, g_hid); SYM(pW20f, g_W20f); SYM(pc0, g_c0); SYM(pY, g_Y);
    SYMH(pxh, g_xh); SYMH(pouth, g_outh); SYMH(pYh, g_Yh);
    SYMH(ph1h, g_h1h); SYMH(ph2h, g_h2h); SYMH(pSh, g_Sh); SYMH(px1h, g_x1h);
    SYMH(pW0h, g_W0h); SYMH(pW1h, g_W1h); SYMH(pW2h, g_W2h);
    SYMH(pW2Th, g_W2Th); SYMH(pW20h, g_W20h);
    SYMH(pWxh, g_Wxh); SYMH(pWhh, g_Whh); SYMH(prW1, g_rW1h);
#undef SYM
#undef SYMH

    k_cvt_all<<<1024, 256>>>(W0, W1, W2o, gWx, gWh, rW1);
    k_transpose<<<512, 256>>>(W2o, pW2Th, Ff, Hh);
    k_c0<<<(Hh + 255)/256, 256>>>(W0, b2o);
    pdl(k_mgemm<EPI_STORE, 0>, dim3(Hh/BN, Hh/BM), NTHR, (size_t)SMEM_TOTAL,
        (const __half*)pW0h, (int)Ff, (const __half*)pW2Th, (int)Ff,
        (const float*)nullptr, pW20f, (int)Hh, (int)Ff, (const float*)nullptr);
    k_cvt<<<512, 256>>>(pW20f, pW20h, Hh*Hh);

    k_prep_x<<<512, 256>>>(fv, fi);
    k_prep_misc<<<512, 256>>>(ts);

    pdl(k_mgemm<EPI_STORE, 0>, dim3(G3F/BN, (Ss*Bb)/BM), NTHR, (size_t)SMEM_TOTAL,
        (const __half*)pxh, (int)Ff, (const __half*)pWxh, (int)Ff,
        gbx, pgx0, (int)G3F, (int)Ff, (const float*)nullptr);

    const int gruBlocks = (Bb*Ff + 255) / 256;
    const dim3 gridH(Hh/BN, MB/BM);
    const dim3 gridYU(Ff/BN, MB/BM);
    const dim3 gridG(G3F/BN, Bb/BM);

    for (int t = 0; t < Ss; t++) {
        const float* dtv = pdt + t*Bb;
        if (t < Ss - 1) {
            if (t == 0)
                k_a1init<<<512, 256>>>(b0);
            else
                pdl(k_mgemm<EPI_A1, 0>, gridH, NTHR, (size_t)SMEM_TOTAL,
                    (const __half*)pYh, (int)Ff, (const __half*)pW0h, (int)Ff,
                    b0, (float*)nullptr, (int)Hh, (int)Ff, (const float*)nullptr);
            for (int k = 0; k < Kk; k++) {
                if (k == 0)
                    pdl(k_mgemm<EPI_H2, 0>, gridH, NTHR, (size_t)SMEM_TOTAL,
                        (const __half*)ph1h, (int)Hh, (const __half*)pW1h, (int)Hh,
                        b1, (float*)nullptr, (int)Hh, (int)Hh, (const float*)nullptr);
                else if (k < Kk - 1)
                    pdl(k_mgemm<EPI_H2, 1>, gridH, NTHR, (size_t)SMEM_TOTAL,
                        (const __half*)ph1h, (int)Hh, (const __half*)pW1h, (int)Hh,
                        b1, (float*)nullptr, (int)Hh, (int)Hh, (const float*)nullptr);
                else
                    pdl(k_mgemm<EPI_H2, 2>, gridH, NTHR, (size_t)SMEM_TOTAL,
                        (const __half*)ph1h, (int)Hh, (const __half*)pW1h, (int)Hh,
                        b1, (float*)nullptr, (int)Hh, (int)Hh, (const float*)nullptr);
                if (k < Kk - 1)
                    pdl(k_mgemm<EPI_DA1, 0>, gridH, NTHR, (size_t)SMEM_TOTAL,
                        (const __half*)ph2h, (int)Hh, (const __half*)pW20h, (int)Hh,
                        (const float*)pc0, (float*)nullptr, (int)Hh, (int)Hh, dtv);
            }
            pdl(k_mgemm<EPI_YUPD, 0>, gridYU, NTHR, (size_t)SMEM_TOTAL,
                (const __half*)pSh, (int)Hh, (const __half*)pW2h, (int)Hh,
                b2o, (float*)nullptr, (int)Ff, (int)Hh, dtv);
        }
        pdl(k_gh0, gridG, NTHR, (size_t)SMEM_TOTAL, gbh);
        pdl(k_gru, dim3(gruBlocks), 256, (size_t)0,
            (const float*)(pgx0 + (size_t)t*Bb*G3F), (const float*)pgh,
            pY, pYh, px1h);
        pdl(k_gxgh1, dim3(G3F/BN, Bb/BM, 2), NTHR, (size_t)SMEM_TOTAL, gbx, gbh);
        pdl(k_gru, dim3(gruBlocks), 256, (size_t)0,
            (const float*)pgx1, (const float*)(pgh + (size_t)Bb*G3F),
            pY + Bb*Ff, pYh + Bb*Ff, pouth + (size_t)t*Bb*Ff);
    }

    pdl(k_mgemm<EPI_LRELU, 0>, dim3(128/BN, (Ss*Bb)/BM), NTHR, (size_t)SMEM_TOTAL,
        (const __half*)pouth, (int)Ff, (const __half*)prW1, (int)Ff,
        rb1, phid, (int)128, (int)Ff, (const float*)nullptr);
    k_pose<<<(Ss*Bb*6 + 127)/128, 128>>>(rW2, rb2, (float*)d_out);

    if (out_size >= Ss*Bb*6 + MB*Ff)
        k_copyY<<<768, 256>>>((float*)d_out + Ss*Bb*6);
}